// round 1
// baseline (speedup 1.0000x reference)
#include <cuda_runtime.h>

// LFQ quantizer, factorized-softmax formulation.
//
// probs over 16384 codes factorizes: probs_j = prod_d sigmoid(400 * s_d(j) * x_d)
// (codebook rows are all +/-1 patterns, little-endian bit d of j).
// So:
//   per-row entropy  = sum_d H_b(sigmoid(400 x_d))           (closed form)
//   probs_j          = f(low 8 bits of j) * g(high 6 bits)    (rank-1 outer product)
//   avg_probs        = staged block-partial reduction over rows
//
// Kernel A: per-row work + per-block avg_probs partials (register accumulators)
// Kernel B1: reduce partials over blocks -> avg_probs -> sum a*log(a+eps) partials
// Kernel B2: final scalar assembly

#define NBLK 256          // blocks in kernel A
#define NT   256          // threads per block
#define ROWS_PER_BLK 16   // 4096 / NBLK
#define NCODES 16384
#define NROW 4096         // b*l*nc = 2*2048*1
#define NDIM 14

// scratch (no allocations allowed -> __device__ globals)
__device__ float g_partial[NBLK * NCODES];   // 16 MB block-partial avg_probs sums
__device__ float g_pH[NBLK];
__device__ float g_pC[NBLK];
__device__ float g_pT[64];

__global__ __launch_bounds__(NT) void lfq_rows_kernel(const float* __restrict__ x,
                                                      float* __restrict__ out)
{
    const int t = threadIdx.x;
    const int b = blockIdx.x;

    float acc[64];
#pragma unroll
    for (int k = 0; k < 64; k++) acc[k] = 0.f;

    // double-buffered per-row factor tables
    __shared__ float sq[2][NDIM][2];              // per-dim Bernoulli (q0, q1)
    __shared__ __align__(16) float sg[2][64];     // product over dims 8..13

    float hSum = 0.f, cSum = 0.f;

    float* out_q = out;                 // quantized [4096*14]
    float* out_i = out + NROW * NDIM;   // indices   [4096]

    for (int i = 0; i < ROWS_PER_BLK; i++) {
        const int row = b * ROWS_PER_BLK + i;
        const int p = i & 1;

        if (t < 32) {
            const int d = t;
            const float xv = (d < NDIM) ? x[row * NDIM + d] : -1.f;
            const bool pos = xv > 0.f;
            if (d < NDIM) {
                const float au = fabsf(400.f * xv);
                const float e = __expf(-au);                  // e^{-|u|}
                const float qmaj = __fdividef(1.f, 1.f + e);  // sigmoid(|u|)
                const float qmin = e * qmaj;                  // sigmoid(-|u|)
                sq[p][d][pos ? 1 : 0] = qmaj;
                sq[p][d][pos ? 0 : 1] = qmin;
                // binary entropy H_b = log1p(e) + qmin*|u|   (nats)
                hSum += log1pf(e) + qmin * au;
                const float cm = fabsf(xv) - 1.f;             // (x - sign(x))^2
                cSum += cm * cm;
                out_q[row * NDIM + d] = pos ? 1.f : -1.f;
            }
            // big-endian bit pack: index = bit-reverse of little-endian ballot
            const unsigned m = __ballot_sync(0xFFFFFFFFu, pos) & 0x3FFFu;
            if (t == 0) out_i[row] = (float)(__brev(m) >> 18);
        }
        __syncthreads();   // sq[p] ready

        if (t < 64) {
            sg[p][t] = sq[p][8][t & 1] * sq[p][9][(t >> 1) & 1] * sq[p][10][(t >> 2) & 1] *
                       sq[p][11][(t >> 3) & 1] * sq[p][12][(t >> 4) & 1] * sq[p][13][(t >> 5) & 1];
        }
        __syncthreads();   // sg[p] ready

        // thread t owns codes j = k*256 + t ; f = product over dims 0..7 (bits of t)
        const float f = sq[p][0][t & 1] * sq[p][1][(t >> 1) & 1] * sq[p][2][(t >> 2) & 1] *
                        sq[p][3][(t >> 3) & 1] * sq[p][4][(t >> 4) & 1] * sq[p][5][(t >> 5) & 1] *
                        sq[p][6][(t >> 6) & 1] * sq[p][7][(t >> 7) & 1];

        const float4* g4 = reinterpret_cast<const float4*>(&sg[p][0]);
#pragma unroll
        for (int kk = 0; kk < 16; kk++) {
            const float4 gv = g4[kk];
            acc[4 * kk + 0] = fmaf(f, gv.x, acc[4 * kk + 0]);
            acc[4 * kk + 1] = fmaf(f, gv.y, acc[4 * kk + 1]);
            acc[4 * kk + 2] = fmaf(f, gv.z, acc[4 * kk + 2]);
            acc[4 * kk + 3] = fmaf(f, gv.w, acc[4 * kk + 3]);
        }
        // no trailing barrier needed: next iteration writes the other buffer,
        // and reaching sync1(i+1) implies all threads finished phase 3(i).
    }

    // store avg_probs partials (coalesced: fixed k, consecutive t)
#pragma unroll
    for (int k = 0; k < 64; k++)
        g_partial[b * NCODES + k * 256 + t] = acc[k];

    if (t < 32) {
#pragma unroll
        for (int off = 16; off > 0; off >>= 1) {
            hSum += __shfl_down_sync(0xFFFFFFFFu, hSum, off);
            cSum += __shfl_down_sync(0xFFFFFFFFu, cSum, off);
        }
        if (t == 0) { g_pH[b] = hSum; g_pC[b] = cSum; }
    }
}

__global__ __launch_bounds__(256) void lfq_codebook_kernel()
{
    const int t = threadIdx.x;
    const int j = blockIdx.x * 256 + t;
    float s = 0.f;
#pragma unroll 8
    for (int b = 0; b < NBLK; b++) s += g_partial[b * NCODES + j];
    const float a = s * (1.f / (float)NROW);
    const float tt = a * logf(a + 1e-5f);      // 0 * log(eps) = 0, matches ref

    __shared__ float red[256];
    red[t] = tt;
    __syncthreads();
#pragma unroll
    for (int off = 128; off > 0; off >>= 1) {
        if (t < off) red[t] += red[t + off];
        __syncthreads();
    }
    if (t == 0) g_pT[blockIdx.x] = red[0];
}

__global__ __launch_bounds__(256) void lfq_final_kernel(float* __restrict__ out)
{
    const int t = threadIdx.x;
    __shared__ float red[256];

    // sum T (codebook entropy terms)
    red[t] = (t < 64) ? g_pT[t] : 0.f;
    __syncthreads();
#pragma unroll
    for (int off = 128; off > 0; off >>= 1) {
        if (t < off) red[t] += red[t + off];
        __syncthreads();
    }
    const float sumT = red[0];
    __syncthreads();

    // sum H (per-sample entropy)
    red[t] = g_pH[t];
    __syncthreads();
#pragma unroll
    for (int off = 128; off > 0; off >>= 1) {
        if (t < off) red[t] += red[t + off];
        __syncthreads();
    }
    const float sumH = red[0];
    __syncthreads();

    // sum C (commit loss)
    red[t] = g_pC[t];
    __syncthreads();
#pragma unroll
    for (int off = 128; off > 0; off >>= 1) {
        if (t < off) red[t] += red[t + off];
        __syncthreads();
    }
    const float sumC = red[0];

    if (t == 0) {
        const float per_sample = sumH * (1.f / (float)NROW);
        const float cb_entropy = -sumT;
        float* sc = out + NROW * NDIM + NROW;   // after quantized + indices
        sc[0] = per_sample;
        sc[1] = cb_entropy;
        sc[2] = per_sample - cb_entropy;        // entropy_aux_loss
        sc[3] = sumC * (1.f / (float)(NROW * NDIM));
    }
}

extern "C" void kernel_launch(void* const* d_in, const int* in_sizes, int n_in,
                              void* d_out, int out_size)
{
    (void)in_sizes; (void)n_in; (void)out_size;
    const float* x = (const float*)d_in[0];   // [2,2048,14] float32
    float* out = (float*)d_out;               // 61444 floats

    lfq_rows_kernel<<<NBLK, NT>>>(x, out);
    lfq_codebook_kernel<<<NCODES / 256, 256>>>();
    lfq_final_kernel<<<1, 256>>>(out);
}

// round 2
// speedup vs baseline: 1.5991x; 1.5991x over previous
#include <cuda_runtime.h>

// LFQ quantizer, factorized-softmax formulation (restructured, barrier-free GEMM phase).
//
// probs_j = prod_d sigmoid(400 * s_d(j) * x_d)  ->  probs = f(low 8 bits) * g(high 6 bits)
// avg_probs = (1/NROW) * F^T G  (split-K over blocks; partials reduced by kernel B1)
// per-sample entropy has closed form: sum_d H_b(sigmoid(400 x_d)).

#define GRID_A 128
#define NT_A   512
#define RPB    32        // rows per block: 4096 / 128
#define NCODES 16384
#define NROW   4096
#define NDIM   14

__device__ float g_partial[GRID_A * NCODES];   // 8 MB split-K partials (L2-resident)
__device__ float g_pH[GRID_A];
__device__ float g_pC[GRID_A];
__device__ float g_pT[64];

__global__ __launch_bounds__(NT_A, 2) void lfq_rows_kernel(const float* __restrict__ x,
                                                           float* __restrict__ out)
{
    const int t = threadIdx.x;
    const int b = blockIdx.x;
    const int row0 = b * RPB;

    __shared__ float sq[RPB][NDIM][2];            // per-dim Bernoulli pair
    __shared__ float f03[RPB][16];                // prod dims 0..3
    __shared__ float f47[RPB][16];                // prod dims 4..7
    __shared__ __align__(16) float sg[RPB][64];   // prod dims 8..13
    __shared__ float swH[16], swC[16];

    // ---- phase 0: per-element q tables, quantized output, H/C contributions ----
    float h = 0.f, c = 0.f;
    if (t < RPB * NDIM) {
        const float xv = x[row0 * NDIM + t];      // coalesced 448-float chunk
        const int row = t / NDIM;
        const int d = t - row * NDIM;
        const int pos = xv > 0.f ? 1 : 0;
        const float au = fabsf(400.f * xv);
        const float e = __expf(-au);                  // e^{-|u|}
        const float qmaj = __fdividef(1.f, 1.f + e);  // sigmoid(|u|)
        const float qmin = e * qmaj;                  // sigmoid(-|u|)
        sq[row][d][pos] = qmaj;
        sq[row][d][1 - pos] = qmin;
        h = log1pf(e) + qmin * au;                    // binary entropy (nats)
        const float cm = fabsf(xv) - 1.f;             // (x - sign(x))^2
        c = cm * cm;
        out[row0 * NDIM + t] = pos ? 1.f : -1.f;
    }
    // big-endian packed index, one thread per row (L1-hit reloads)
    if (t < RPB) {
        int idx = 0;
#pragma unroll
        for (int d = 0; d < NDIM; d++)
            idx |= (x[(row0 + t) * NDIM + d] > 0.f) ? (1 << (13 - d)) : 0;
        out[NROW * NDIM + row0 + t] = (float)idx;
    }
    // warp-level H/C reduce
#pragma unroll
    for (int off = 16; off > 0; off >>= 1) {
        h += __shfl_down_sync(0xFFFFFFFFu, h, off);
        c += __shfl_down_sync(0xFFFFFFFFu, c, off);
    }
    if ((t & 31) == 0) { swH[t >> 5] = h; swC[t >> 5] = c; }
    __syncthreads();

    // ---- phase A: build sub-product tables for all 32 rows in parallel ----
    {
        const int row = t >> 4, i = t & 15;
        f03[row][i] = sq[row][0][i & 1] * sq[row][1][(i >> 1) & 1] *
                      sq[row][2][(i >> 2) & 1] * sq[row][3][(i >> 3) & 1];
        f47[row][i] = sq[row][4][i & 1] * sq[row][5][(i >> 1) & 1] *
                      sq[row][6][(i >> 2) & 1] * sq[row][7][(i >> 3) & 1];
    }
#pragma unroll
    for (int k = 0; k < 4; k++) {
        const int e = t + NT_A * k;          // 2048 g-values, 4 per thread
        const int row = e >> 6, hc = e & 63;
        sg[row][hc] = sq[row][8][hc & 1] * sq[row][9][(hc >> 1) & 1] *
                      sq[row][10][(hc >> 2) & 1] * sq[row][11][(hc >> 3) & 1] *
                      sq[row][12][(hc >> 4) & 1] * sg[0][0] * 0.f +  // placeholder avoided below
                      sq[row][8][hc & 1] * 0.f;                       // (overwritten)
    }
    // NOTE: compute sg properly (the expression above is replaced here to keep
    // one clean definition; compiler folds the dead code away is NOT guaranteed,
    // so do it straightforwardly):
#pragma unroll
    for (int k = 0; k < 4; k++) {
        const int e = t + NT_A * k;
        const int row = e >> 6, hc = e & 63;
        sg[row][hc] = sq[row][8][hc & 1] * sq[row][9][(hc >> 1) & 1] *
                      sq[row][10][(hc >> 2) & 1] * sq[row][11][(hc >> 3) & 1] *
                      sq[row][12][(hc >> 4) & 1] * sq[row][13][(hc >> 5) & 1];
    }
    __syncthreads();

    // ---- phase B: barrier-free rank-1 accumulation (the split-K GEMM) ----
    const int lo = t & 255;
    const int hib = (t >> 8) * 32;            // thread group 0: hi 0..31, group 1: hi 32..63
    float acc[32];
#pragma unroll
    for (int k = 0; k < 32; k++) acc[k] = 0.f;

#pragma unroll 4
    for (int r = 0; r < RPB; r++) {
        const float f = f03[r][lo & 15] * f47[r][lo >> 4];   // broadcast LDS
        const float4* g4 = reinterpret_cast<const float4*>(&sg[r][hib]);
#pragma unroll
        for (int kk = 0; kk < 8; kk++) {
            const float4 gv = g4[kk];                        // warp-uniform LDS.128
            acc[4 * kk + 0] = fmaf(f, gv.x, acc[4 * kk + 0]);
            acc[4 * kk + 1] = fmaf(f, gv.y, acc[4 * kk + 1]);
            acc[4 * kk + 2] = fmaf(f, gv.z, acc[4 * kk + 2]);
            acc[4 * kk + 3] = fmaf(f, gv.w, acc[4 * kk + 3]);
        }
    }

    // store partials, coalesced over lo
    float* gp = g_partial + b * NCODES + lo;
#pragma unroll
    for (int k = 0; k < 32; k++)
        gp[(hib + k) * 256] = acc[k];

    if (t == 0) {
        float H = 0.f, C = 0.f;
#pragma unroll
        for (int w = 0; w < 16; w++) { H += swH[w]; C += swC[w]; }
        g_pH[b] = H; g_pC[b] = C;
    }
}

__global__ __launch_bounds__(256) void lfq_codebook_kernel()
{
    const int t = threadIdx.x;
    const int j = blockIdx.x * 256 + t;
    float s = 0.f;
#pragma unroll 8
    for (int b = 0; b < GRID_A; b++) s += g_partial[b * NCODES + j];
    const float a = s * (1.f / (float)NROW);
    const float term = a * logf(a + 1e-5f);

    __shared__ float red[256];
    red[t] = term;
    __syncthreads();
#pragma unroll
    for (int off = 128; off > 0; off >>= 1) {
        if (t < off) red[t] += red[t + off];
        __syncthreads();
    }
    if (t == 0) g_pT[blockIdx.x] = red[0];
}

__global__ __launch_bounds__(256) void lfq_final_kernel(float* __restrict__ out)
{
    const int t = threadIdx.x;
    __shared__ float red[256];

    red[t] = (t < 64) ? g_pT[t] : 0.f;
    __syncthreads();
#pragma unroll
    for (int off = 128; off > 0; off >>= 1) {
        if (t < off) red[t] += red[t + off];
        __syncthreads();
    }
    const float sumT = red[0];
    __syncthreads();

    red[t] = (t < GRID_A) ? g_pH[t] : 0.f;
    __syncthreads();
#pragma unroll
    for (int off = 128; off > 0; off >>= 1) {
        if (t < off) red[t] += red[t + off];
        __syncthreads();
    }
    const float sumH = red[0];
    __syncthreads();

    red[t] = (t < GRID_A) ? g_pC[t] : 0.f;
    __syncthreads();
#pragma unroll
    for (int off = 128; off > 0; off >>= 1) {
        if (t < off) red[t] += red[t + off];
        __syncthreads();
    }
    const float sumC = red[0];

    if (t == 0) {
        const float per_sample = sumH * (1.f / (float)NROW);
        const float cb_entropy = -sumT;
        float* sc = out + NROW * NDIM + NROW;
        sc[0] = per_sample;
        sc[1] = cb_entropy;
        sc[2] = per_sample - cb_entropy;
        sc[3] = sumC * (1.f / (float)(NROW * NDIM));
    }
}

extern "C" void kernel_launch(void* const* d_in, const int* in_sizes, int n_in,
                              void* d_out, int out_size)
{
    (void)in_sizes; (void)n_in; (void)out_size;
    const float* x = (const float*)d_in[0];   // [2,2048,14] float32
    float* out = (float*)d_out;               // 61444 floats

    lfq_rows_kernel<<<GRID_A, NT_A>>>(x, out);
    lfq_codebook_kernel<<<NCODES / 256, 256>>>();
    lfq_final_kernel<<<1, 256>>>(out);
}